// round 13
// baseline (speedup 1.0000x reference)
#include <cuda_runtime.h>
#include <cuda_bf16.h>

// FocalLoss: input [N,C]=[1048576,80] fp32, target [N] int32, gamma=2.
// out = mean_n sum_c -(1-pt)^2*logpt, pt = sigmoid(sign*x).
//
// R13 = R12 (59.9us) with the core rebuilt on MUFU.TANH:
//   pt = 0.5 + 0.5*tanh(x/2);  1-pt = 0.5 - 0.5*tanh(x/2)
//   elem contribution (in log2 units, negative) = (1-pt)^2 * log2(pt)
// 7 ops/elem (2 MUFU + 5 fma-pipe) vs 11 previously. Same pipelined
// correction gather, 16-row tiles, single-wave 1184x256 grid.

#define N_ROWS   1048576
#define C_CLS    80
#define ROWS_PER_TILE 16
#define F4_PER_TILE   320          // 16 rows * 20 float4
#define N_TILES  (N_ROWS / ROWS_PER_TILE)   // 65536
#define NBLOCKS  1184              // 148 SMs * 8 CTAs, single wave
#define NTHREADS 256
#define WARPS_PER_BLOCK (NTHREADS / 32)
#define LN2      0.6931471805599453

__device__ double g_partials[NBLOCKS];
__device__ unsigned int g_count;

__device__ __forceinline__ float tanhf_(float x) {
    float y; asm("tanh.approx.f32 %0, %1;" : "=f"(y) : "f"(x)); return y;
}
__device__ __forceinline__ float lg2f_(float x) {
    float y; asm("lg2.approx.f32 %0, %1;" : "=f"(y) : "f"(x)); return y;
}

// core_h(h) with h = x/2: returns (1-pt)^2 * log2(pt)  (negative).
__device__ __forceinline__ float focal_core_h(float h) {
    float t  = tanhf_(h);                    // MUFU.TANH
    float q  = fmaf(-0.5f, t, 0.5f);         // 1-pt = sigma(-x)
    float pt = fmaf( 0.5f, t, 0.5f);         // sigma(x)
    float pp = q * q;
    return pp * lg2f_(pt);                   // MUFU.LG2; folds to FFMA w/ acc
}

__global__ __launch_bounds__(NTHREADS, 8) void focal_fused_kernel(
    const float* __restrict__ inp,
    const int* __restrict__ tgt,
    float* __restrict__ out)
{
    const unsigned lane   = threadIdx.x & 31u;
    const unsigned gwarp  = blockIdx.x * WARPS_PER_BLOCK + (threadIdx.x >> 5);
    const unsigned nwarps = gridDim.x * WARPS_PER_BLOCK;   // 9472

    const float4* __restrict__ inp4 = (const float4*)inp;

    float fs0 = 0.0f, fs1 = 0.0f;    // accumulate NEGATIVE log2-space values

    for (unsigned tile = gwarp; tile < (unsigned)N_TILES; tile += nwarps) {
        const unsigned row0 = tile * ROWS_PER_TILE;
        const unsigned base = tile * (unsigned)F4_PER_TILE + lane;

        // stage 1: issue target-index load early (lanes 0-15 own one row each)
        int t = 0;
        if (lane < 16u) t = __ldg(&tgt[row0 + lane]);

        // non-target element v: x = -v -> h = -v/2
        #pragma unroll 5
        for (unsigned k = 0; k < 5u; k++) {
            float4 v = __ldg(&inp4[base + k * 32u]);
            fs0 += focal_core_h(v.x * -0.5f);
            fs1 += focal_core_h(v.y * -0.5f);
            fs0 += focal_core_h(v.z * -0.5f);
            fs1 += focal_core_h(v.w * -0.5f);
        }

        // stage 2: dependent gather; line is L2-resident (streamed just above)
        float tv = 0.0f;
        if (lane < 16u)
            tv = __ldg(&inp[(row0 + lane) * (unsigned)C_CLS + (unsigned)t]);

        #pragma unroll 5
        for (unsigned k = 5u; k < 10u; k++) {
            float4 v = __ldg(&inp4[base + k * 32u]);
            fs0 += focal_core_h(v.x * -0.5f);
            fs1 += focal_core_h(v.y * -0.5f);
            fs0 += focal_core_h(v.z * -0.5f);
            fs1 += focal_core_h(v.w * -0.5f);
        }

        // stage 3: correction math (target uses h=+v/2; remove the -v/2 term)
        if (lane < 16u)
            fs0 += focal_core_h(tv * 0.5f) - focal_core_h(tv * -0.5f);
    }

    float fsum = fs0 + fs1;

    #pragma unroll
    for (int off = 16; off > 0; off >>= 1)
        fsum += __shfl_down_sync(0xFFFFFFFFu, fsum, off);

    __shared__ double s_warp[WARPS_PER_BLOCK];
    int wid = threadIdx.x >> 5;
    if (lane == 0) s_warp[wid] = (double)fsum;
    __syncthreads();

    __shared__ bool s_last;
    if (threadIdx.x == 0) {
        double bsum = 0.0;
        #pragma unroll
        for (int w = 0; w < WARPS_PER_BLOCK; w++) bsum += s_warp[w];
        g_partials[blockIdx.x] = bsum;
        __threadfence();
        unsigned done = atomicAdd(&g_count, 1u);
        s_last = (done == gridDim.x - 1);
    }
    __syncthreads();

    if (s_last) {
        __threadfence();
        __shared__ double s_red[NTHREADS];
        double v = 0.0;
        for (int k = threadIdx.x; k < NBLOCKS; k += NTHREADS)
            v += g_partials[k];
        s_red[threadIdx.x] = v;
        __syncthreads();
        #pragma unroll
        for (int off = NTHREADS / 2; off > 0; off >>= 1) {
            if (threadIdx.x < off) s_red[threadIdx.x] += s_red[threadIdx.x + off];
            __syncthreads();
        }
        if (threadIdx.x == 0) {
            // accumulated sum is negative (log2 space); loss = -sum*ln2/N
            out[0] = (float)(s_red[0] * -LN2 / (double)N_ROWS);
            g_count = 0;
        }
    }
}

extern "C" void kernel_launch(void* const* d_in, const int* in_sizes, int n_in,
                              void* d_out, int out_size)
{
    const float* inp = (const float*)d_in[0];
    const int* tgt   = (const int*)d_in[1];
    float* out       = (float*)d_out;

    focal_fused_kernel<<<NBLOCKS, NTHREADS>>>(inp, tgt, out);
}

// round 14
// speedup vs baseline: 1.0479x; 1.0479x over previous
#include <cuda_runtime.h>
#include <cuda_bf16.h>

// FocalLoss: input [N,C]=[1048576,80] fp32, target [N] int32, gamma=2.
// out = mean_n sum_c -(1-pt)^2*logpt, pt = sigmoid(sign*x).
//
// R14 = R13 (60.2us, at ~97% of observed DRAM ceiling) + streaming cache
// hints on the read-once bulk loads (evict-first), keeping the correction
// gather on the default path so its L2-resident line isn't bypassed.
// Core: pt = 0.5 + 0.5*tanh(x/2); contribution = (1-pt)^2 * log2(pt)
// (negative, log2 space); 2 MUFU + 5 fma-pipe ops per element.

#define N_ROWS   1048576
#define C_CLS    80
#define ROWS_PER_TILE 16
#define F4_PER_TILE   320          // 16 rows * 20 float4
#define N_TILES  (N_ROWS / ROWS_PER_TILE)   // 65536
#define NBLOCKS  1184              // 148 SMs * 8 CTAs, single wave
#define NTHREADS 256
#define WARPS_PER_BLOCK (NTHREADS / 32)
#define LN2      0.6931471805599453

__device__ double g_partials[NBLOCKS];
__device__ unsigned int g_count;

__device__ __forceinline__ float tanhf_(float x) {
    float y; asm("tanh.approx.f32 %0, %1;" : "=f"(y) : "f"(x)); return y;
}
__device__ __forceinline__ float lg2f_(float x) {
    float y; asm("lg2.approx.f32 %0, %1;" : "=f"(y) : "f"(x)); return y;
}

// read-once streaming load: non-coherent path + evict-first
__device__ __forceinline__ float4 ldg_stream4(const float4* p) {
    float4 v;
    asm volatile("ld.global.nc.L1::no_allocate.v4.f32 {%0,%1,%2,%3}, [%4];"
                 : "=f"(v.x), "=f"(v.y), "=f"(v.z), "=f"(v.w) : "l"(p));
    return v;
}

// core_h(h) with h = x/2: returns (1-pt)^2 * log2(pt)  (negative).
__device__ __forceinline__ float focal_core_h(float h) {
    float t  = tanhf_(h);                    // MUFU.TANH
    float q  = fmaf(-0.5f, t, 0.5f);         // 1-pt = sigma(-x)
    float pt = fmaf( 0.5f, t, 0.5f);         // sigma(x)
    float pp = q * q;
    return pp * lg2f_(pt);                   // MUFU.LG2; folds to FFMA w/ acc
}

__global__ __launch_bounds__(NTHREADS, 8) void focal_fused_kernel(
    const float* __restrict__ inp,
    const int* __restrict__ tgt,
    float* __restrict__ out)
{
    const unsigned lane   = threadIdx.x & 31u;
    const unsigned gwarp  = blockIdx.x * WARPS_PER_BLOCK + (threadIdx.x >> 5);
    const unsigned nwarps = gridDim.x * WARPS_PER_BLOCK;   // 9472

    const float4* __restrict__ inp4 = (const float4*)inp;

    float fs0 = 0.0f, fs1 = 0.0f;    // negative log2-space accumulators

    for (unsigned tile = gwarp; tile < (unsigned)N_TILES; tile += nwarps) {
        const unsigned row0 = tile * ROWS_PER_TILE;
        const unsigned base = tile * (unsigned)F4_PER_TILE + lane;

        // stage 1: issue target-index load early (lanes 0-15 own one row each)
        int t = 0;
        if (lane < 16u) t = __ldg(&tgt[row0 + lane]);

        // non-target element v: x = -v -> h = -v/2
        #pragma unroll 5
        for (unsigned k = 0; k < 5u; k++) {
            float4 v = ldg_stream4(&inp4[base + k * 32u]);
            fs0 += focal_core_h(v.x * -0.5f);
            fs1 += focal_core_h(v.y * -0.5f);
            fs0 += focal_core_h(v.z * -0.5f);
            fs1 += focal_core_h(v.w * -0.5f);
        }

        // stage 2: dependent gather; default cache path (line is L2-resident)
        float tv = 0.0f;
        if (lane < 16u)
            tv = __ldg(&inp[(row0 + lane) * (unsigned)C_CLS + (unsigned)t]);

        #pragma unroll 5
        for (unsigned k = 5u; k < 10u; k++) {
            float4 v = ldg_stream4(&inp4[base + k * 32u]);
            fs0 += focal_core_h(v.x * -0.5f);
            fs1 += focal_core_h(v.y * -0.5f);
            fs0 += focal_core_h(v.z * -0.5f);
            fs1 += focal_core_h(v.w * -0.5f);
        }

        // stage 3: correction math (target term uses h=+v/2; remove -v/2 term)
        if (lane < 16u)
            fs0 += focal_core_h(tv * 0.5f) - focal_core_h(tv * -0.5f);
    }

    float fsum = fs0 + fs1;

    #pragma unroll
    for (int off = 16; off > 0; off >>= 1)
        fsum += __shfl_down_sync(0xFFFFFFFFu, fsum, off);

    __shared__ double s_warp[WARPS_PER_BLOCK];
    int wid = threadIdx.x >> 5;
    if (lane == 0) s_warp[wid] = (double)fsum;
    __syncthreads();

    __shared__ bool s_last;
    if (threadIdx.x == 0) {
        double bsum = 0.0;
        #pragma unroll
        for (int w = 0; w < WARPS_PER_BLOCK; w++) bsum += s_warp[w];
        g_partials[blockIdx.x] = bsum;
        __threadfence();
        unsigned done = atomicAdd(&g_count, 1u);
        s_last = (done == gridDim.x - 1);
    }
    __syncthreads();

    if (s_last) {
        __threadfence();
        __shared__ double s_red[NTHREADS];
        double v = 0.0;
        for (int k = threadIdx.x; k < NBLOCKS; k += NTHREADS)
            v += g_partials[k];
        s_red[threadIdx.x] = v;
        __syncthreads();
        #pragma unroll
        for (int off = NTHREADS / 2; off > 0; off >>= 1) {
            if (threadIdx.x < off) s_red[threadIdx.x] += s_red[threadIdx.x + off];
            __syncthreads();
        }
        if (threadIdx.x == 0) {
            out[0] = (float)(s_red[0] * -LN2 / (double)N_ROWS);
            g_count = 0;
        }
    }
}

extern "C" void kernel_launch(void* const* d_in, const int* in_sizes, int n_in,
                              void* d_out, int out_size)
{
    const float* inp = (const float*)d_in[0];
    const int* tgt   = (const int*)d_in[1];
    float* out       = (float*)d_out;

    focal_fused_kernel<<<NBLOCKS, NTHREADS>>>(inp, tgt, out);
}